// round 9
// baseline (speedup 1.0000x reference)
#include <cuda_runtime.h>
#include <cstdint>

#define T_STEPS   4096
#define HID       2048
#define IN_DIM    128
#define NCTA      128
#define ROWS_CTA  16
#define NTHREADS  512
#define LEAK      0.9f
#define TT        32      // prologue time-tile

typedef unsigned long long u64;

// Persistent cross-replay state. Tags are MONOTONIC (base advances by T_STEPS per
// launch, never resets) so graph replays need no reset pass.
__device__ u64   g_tagged[2][HID];          // (tag<<32) | float_bits(act) — fused flag+data
__device__ int   g_base[NCTA][32];          // per-CTA base counter, 128B sector each
__device__ float g_ip[T_STEPS * HID];       // precomputed input projection (32 MB, static)

// SCALAR 8B relaxed load — the champion used these; both regressions (R4/R8)
// used v2.b64 128-bit strong loads. This round isolates that variable.
__device__ __forceinline__ u64 ld_relaxed64(const u64* p) {
    u64 v;
    asm volatile("ld.relaxed.gpu.global.b64 %0, [%1];" : "=l"(v) : "l"(p));
    return v;
}
__device__ __forceinline__ void st_relaxed64(u64* p, u64 v) {
    asm volatile("st.relaxed.gpu.global.b64 [%0], %1;" :: "l"(p), "l"(v));
}
// tanh(x) = sign(x) * (1 - 2/(exp(2|x|)+1)); MUFU-based, validated rel_err ~5e-7.
__device__ __forceinline__ float fast_tanh(float x) {
    float e = __expf(2.0f * fabsf(x));
    float r = 1.0f - __fdividef(2.0f, e + 1.0f);
    return copysignf(r, x);
}

__global__ void __launch_bounds__(NTHREADS, 1)
reservoir_kernel(const float* __restrict__ input,   // [T, IN_DIM]
                 const float* __restrict__ w_ih,    // [HID, IN_DIM]
                 const float* __restrict__ b_ih,    // [HID]
                 const float* __restrict__ w_hh,    // [HID, HID]
                 float* __restrict__ out)           // [2, T, HID] (act, hid)
{
    __shared__ __align__(16) float tile[TT][132];             // prologue input tile
    __shared__ __align__(16) float w_ih_s[ROWS_CTA][132];
    __shared__ __align__(16) float red_s[2][ROWS_CTA][16];    // parity double-buffered
    __shared__ float b_s[ROWS_CTA];
    __shared__ int   base_s;

    const int tid  = threadIdx.x;
    const int cta  = blockIdx.x;
    const int r0   = cta * ROWS_CTA;
    const int warp = tid >> 5;       // 0..15 — warp w's lane 0 owns row w in Phase C
    const int lane = tid & 31;
    // Thread owns cols [4*tid, 4*tid+4) for ALL 16 rows: each tagged word is
    // polled by exactly ONE thread in the CTA (champion traffic, staggered start).

    // ---- one-time setup ----
    {
        const float4* w4p = (const float4*)(w_ih + r0 * IN_DIM);
        for (int i = tid; i < ROWS_CTA * (IN_DIM / 4); i += NTHREADS) {
            int row = i >> 5, c = i & 31;
            *(float4*)&w_ih_s[row][4 * c] = w4p[i];
        }
    }
    if (tid < ROWS_CTA) b_s[tid] = b_ih[r0 + tid];
    if (tid == 0) base_s = g_base[cta][0];

    // w_hh[r0+r][4*tid .. 4*tid+3] for r = 0..15 -> 64 registers
    float4 w4[ROWS_CTA];
    {
        const float4* w_hh4 = (const float4*)w_hh;
        #pragma unroll
        for (int r = 0; r < ROWS_CTA; r++)
            w4[r] = w_hh4[(size_t)(r0 + r) * (HID / 4) + tid];
    }

    // ---- PROLOGUE: inp_proj for this CTA's 16 rows, all T steps -> g_ip ----
    {
        const int trow = tid >> 4;          // 0..31
        const int row  = tid & 15;
        for (int t0 = 0; t0 < T_STEPS; t0 += TT) {
            __syncthreads();
            const float4* in4 = (const float4*)(input + t0 * IN_DIM);
            for (int i = tid; i < TT * (IN_DIM / 4); i += NTHREADS) {
                int tt = i >> 5, c = i & 31;
                *(float4*)&tile[tt][4 * c] = in4[i];
            }
            __syncthreads();
            float acc = 0.0f;
            #pragma unroll
            for (int j = 0; j < 32; j++) {
                float4 uv = *(const float4*)&tile[trow][4 * j];
                float4 wv = *(const float4*)&w_ih_s[row][4 * j];
                acc = fmaf(uv.x, wv.x, fmaf(uv.y, wv.y,
                      fmaf(uv.z, wv.z, fmaf(uv.w, wv.w, acc))));
            }
            g_ip[(size_t)(t0 + trow) * HID + r0 + row] = acc + b_s[row];
        }
    }
    __syncthreads();
    const int base = base_s;

    float* __restrict__ out_act = out;
    float* __restrict__ out_hid = out + (size_t)T_STEPS * HID;

    // Per-warp Phase C state (lane 0 of each warp owns row `warp`)
    float hid_r = 0.0f;
    float ipc = 0.0f, ipn = 0.0f;
    if (lane == 0) {
        ipc = __ldcg(&g_ip[(size_t)0 * HID + r0 + warp]);
        ipn = __ldcg(&g_ip[(size_t)1 * HID + r0 + warp]);
    }

    for (int t = 0; t < T_STEPS; t++) {
        // ---- Poll OWN 4 tagged words with 4 SCALAR 8B relaxed loads (MLP=4).
        // Fused tag+data = one L2 round trip; exact-match monotonic tags make
        // relaxed loads safe. No bar A, no smem rebroadcast.
        float4 a4;
        if (t > 0) {
            const unsigned exp_tag = (unsigned)(base + t);
            const u64* src = &g_tagged[(t - 1) & 1][4 * tid];
            u64 w0, w1, w2, w3;
            for (;;) {
                w0 = ld_relaxed64(src + 0);
                w1 = ld_relaxed64(src + 1);
                w2 = ld_relaxed64(src + 2);
                w3 = ld_relaxed64(src + 3);
                if ((unsigned)(w0 >> 32) == exp_tag && (unsigned)(w1 >> 32) == exp_tag &&
                    (unsigned)(w2 >> 32) == exp_tag && (unsigned)(w3 >> 32) == exp_tag)
                    break;
            }
            a4.x = __uint_as_float((unsigned)w0);
            a4.y = __uint_as_float((unsigned)w1);
            a4.z = __uint_as_float((unsigned)w2);
            a4.w = __uint_as_float((unsigned)w3);
        } else {
            a4 = make_float4(0.f, 0.f, 0.f, 0.f);
        }

        // ---- Phase B: 16 rows x 4 cols on register weights ----
        float v[ROWS_CTA];
        #pragma unroll
        for (int r = 0; r < ROWS_CTA; r++)
            v[r] = fmaf(w4[r].x, a4.x,
                   fmaf(w4[r].y, a4.y,
                   fmaf(w4[r].z, a4.z, w4[r].w * a4.w)));

        // select-then-shuffle fold: 16 accumulators -> lane (row) holds the
        // warp-wide sum for its row after the final offset-16 add.
        {
            const int b1 = lane & 1;
            #pragma unroll
            for (int k = 0; k < 8; k++) {
                float give = b1 ? v[2 * k] : v[2 * k + 1];
                float got  = __shfl_xor_sync(0xFFFFFFFFu, give, 1);
                v[k] = (b1 ? v[2 * k + 1] : v[2 * k]) + got;
            }
            const int b2 = (lane >> 1) & 1;
            #pragma unroll
            for (int k = 0; k < 4; k++) {
                float give = b2 ? v[2 * k] : v[2 * k + 1];
                float got  = __shfl_xor_sync(0xFFFFFFFFu, give, 2);
                v[k] = (b2 ? v[2 * k + 1] : v[2 * k]) + got;
            }
            const int b3 = (lane >> 2) & 1;
            #pragma unroll
            for (int k = 0; k < 2; k++) {
                float give = b3 ? v[2 * k] : v[2 * k + 1];
                float got  = __shfl_xor_sync(0xFFFFFFFFu, give, 4);
                v[k] = (b3 ? v[2 * k + 1] : v[2 * k]) + got;
            }
            const int b4 = (lane >> 3) & 1;
            {
                float give = b4 ? v[0] : v[1];
                float got  = __shfl_xor_sync(0xFFFFFFFFu, give, 8);
                v[0] = (b4 ? v[1] : v[0]) + got;
            }
            v[0] += __shfl_xor_sync(0xFFFFFFFFu, v[0], 16);
        }
        if (lane < ROWS_CTA) red_s[t & 1][lane][warp] = v[0];
        __syncthreads();                                 // bar B (only barrier/step)

        // ---- Phase C: DISTRIBUTED — every warp's lane 0 reduces + publishes
        // its own row. Uniform ~180-cyc delay across all warps instead of a
        // serial warp-0 tail gating the whole CTA.
        if (lane == 0) {
            const int row = warp;
            float4 s0 = *(const float4*)&red_s[t & 1][row][0];
            float4 s1 = *(const float4*)&red_s[t & 1][row][4];
            float4 s2 = *(const float4*)&red_s[t & 1][row][8];
            float4 s3 = *(const float4*)&red_s[t & 1][row][12];
            float sx = ((s0.x + s1.x) + (s2.x + s3.x)) + ((s0.y + s1.y) + (s2.y + s3.y));
            float sy = ((s0.z + s1.z) + (s2.z + s3.z)) + ((s0.w + s1.w) + (s2.w + s3.w));
            float tot = sx + sy;

            const float nh = (1.0f - LEAK) * hid_r + LEAK * (ipc + tot);
            const float na = fast_tanh(nh);
            hid_r = nh;

            const int gr = r0 + row;
            st_relaxed64(&g_tagged[t & 1][gr],
                         ((u64)(unsigned)(base + t + 1) << 32) | (u64)__float_as_uint(na));
            out_act[(size_t)t * HID + gr] = na;
            out_hid[(size_t)t * HID + gr] = nh;

            // advance ip pipeline (slack: consumed 2 steps from issue)
            ipc = ipn;
            int tn = (t + 2 < T_STEPS) ? t + 2 : T_STEPS - 1;
            ipn = __ldcg(&g_ip[(size_t)tn * HID + gr]);
        }
        // No trailing barrier. red_s slot (t&1) rewritten at t+2, which follows
        // the writer's detect(t+2) <= all CTAs' publish(t+1) <= this CTA's
        // barB(t+1) <= every warp arrived, i.e., after all Phase C(t) reads.
        // g_tagged slot overwrite (tag t+3, producer step t+2) <= producer's
        // detect(t+2) <= every CTA published t+1 <= every CTA's barB(t+1) <=
        // every consumer thread finished its tag-(t+1) poll — nobody is lapped.
    }

    if (tid == 0) g_base[cta][0] = base + T_STEPS;   // advance tags for next replay
}

extern "C" void kernel_launch(void* const* d_in, const int* in_sizes, int n_in,
                              void* d_out, int out_size) {
    const float* input = (const float*)d_in[0];   // [4096, 128]
    const float* w_ih  = (const float*)d_in[1];   // [2048, 128]
    const float* b_ih  = (const float*)d_in[2];   // [2048]
    const float* w_hh  = (const float*)d_in[3];   // [2048, 2048]
    float* out = (float*)d_out;                   // [2, 4096, 2048]

    reservoir_kernel<<<NCTA, NTHREADS>>>(input, w_ih, b_ih, w_hh, out);
}

// round 10
// speedup vs baseline: 4.8159x; 4.8159x over previous
#include <cuda_runtime.h>
#include <cstdint>

#define T_STEPS   4096
#define HID       2048
#define IN_DIM    128
#define NCTA      128
#define ROWS_CTA  16
#define NTHREADS  1024
#define LEAK      0.9f
#define TT        64      // prologue time-tile

typedef unsigned long long u64;

// Persistent cross-replay state. Tags are MONOTONIC (base advances by T_STEPS per
// launch, never resets) so graph replays need no reset pass.
__device__ u64   g_tagged[2][HID];          // (tag<<32) | float_bits(act)
__device__ int   g_base[NCTA][32];          // per-CTA base counter, 128B sector each
__device__ float g_ip[T_STEPS * HID];       // precomputed input projection (32 MB, static)

__device__ __forceinline__ u64 ld_relaxed64(const u64* p) {
    u64 v;
    asm volatile("ld.relaxed.gpu.global.b64 %0, [%1];" : "=l"(v) : "l"(p));
    return v;
}
__device__ __forceinline__ void st_relaxed64(u64* p, u64 v) {
    asm volatile("st.relaxed.gpu.global.b64 [%0], %1;" :: "l"(p), "l"(v));
}
// tanh(x) = sign(x) * (1 - 2/(exp(2|x|)+1)); MUFU-based, validated rel_err ~5e-7.
__device__ __forceinline__ float fast_tanh(float x) {
    float e = __expf(2.0f * fabsf(x));
    float r = 1.0f - __fdividef(2.0f, e + 1.0f);
    return copysignf(r, x);
}

__global__ void __launch_bounds__(NTHREADS, 1)
reservoir_kernel(const float* __restrict__ input,   // [T, IN_DIM]
                 const float* __restrict__ w_ih,    // [HID, IN_DIM]
                 const float* __restrict__ b_ih,    // [HID]
                 const float* __restrict__ w_hh,    // [HID, HID]
                 float* __restrict__ out)           // [2, T, HID] (act, hid)
{
    // 33 KB pool: prologue overlays the input tile on top of main-loop a_sf/red_s
    __shared__ __align__(16) float shpool[TT * 132];          // 33792 B
    __shared__ __align__(16) float w_ih_s[ROWS_CTA][132];     // padded rows
    __shared__ float hid_s[ROWS_CTA];
    __shared__ float b_s[ROWS_CTA];
    __shared__ int   base_s;

    float*        a_sf  = shpool;                              // [2048] act broadcast
    float (*red_s)[16]  = (float(*)[16])(shpool + 2048);       // [16][16]
    float (*tile)[132]  = (float(*)[132])shpool;               // prologue overlay

    const int tid  = threadIdx.x;
    const int cta  = blockIdx.x;
    const int r0   = cta * ROWS_CTA;
    const int half = tid >> 9;       // 0: local rows 0..7, 1: rows 8..15
    const int slot = tid & 511;      // cols [4*slot, 4*slot+4)
    const int warp = tid >> 5;
    const int lane = tid & 31;

    // ---- one-time setup ----
    {
        const float4* w4p = (const float4*)(w_ih + r0 * IN_DIM);
        for (int i = tid; i < ROWS_CTA * (IN_DIM / 4); i += NTHREADS) {
            int row = i >> 5, c = i & 31;
            *(float4*)&w_ih_s[row][4 * c] = w4p[i];
        }
    }
    if (tid < ROWS_CTA) { b_s[tid] = b_ih[r0 + tid]; hid_s[tid] = 0.0f; }
    if (tid == 0) base_s = g_base[cta][0];

    // w_hh rows for this CTA -> registers (128 KB/CTA)
    float4 w4[8];
    {
        const float4* w_hh4 = (const float4*)w_hh;
        const int rbase = r0 + half * 8;
        #pragma unroll
        for (int i = 0; i < 8; i++)
            w4[i] = w_hh4[(size_t)(rbase + i) * (HID / 4) + slot];
    }

    // ---- PROLOGUE: inp_proj for this CTA's 16 rows, all T steps -> g_ip ----
    {
        const int trow = tid >> 4;          // 0..63
        const int row  = tid & 15;
        for (int t0 = 0; t0 < T_STEPS; t0 += TT) {
            __syncthreads();
            const float4* in4 = (const float4*)(input + t0 * IN_DIM);
            for (int i = tid; i < TT * (IN_DIM / 4); i += NTHREADS) {
                int tt = i >> 5, c = i & 31;
                *(float4*)&tile[tt][4 * c] = in4[i];
            }
            __syncthreads();
            float acc = 0.0f;
            #pragma unroll
            for (int j = 0; j < 32; j++) {
                float4 uv = *(const float4*)&tile[trow][4 * j];
                float4 wv = *(const float4*)&w_ih_s[row][4 * j];
                acc = fmaf(uv.x, wv.x, fmaf(uv.y, wv.y,
                      fmaf(uv.z, wv.z, fmaf(uv.w, wv.w, acc))));
            }
            g_ip[(size_t)(t0 + trow) * HID + r0 + row] = acc + b_s[row];
        }
    }
    __syncthreads();    // g_ip slice visible; tile overlay free for a_sf
    const int base = base_s;

    float* __restrict__ out_act = out;
    float* __restrict__ out_hid = out + (size_t)T_STEPS * HID;

    // ip register pipeline for Phase C threads (consume t, hold t+1, fetch t+2)
    float ipc = 0.0f, ipn = 0.0f;
    if (tid < ROWS_CTA) {
        ipc = __ldcg(&g_ip[(size_t)0 * HID + r0 + tid]);
        ipn = __ldcg(&g_ip[(size_t)1 * HID + r0 + tid]);
    }

    for (int t = 0; t < T_STEPS; t++) {
        // ---- Poll tagged acts of step t-1 (ALL threads, 2 u64 each).
        // CONTIGUOUS mapping: thread tid polls words {tid, tid+1024}. Each
        // warp's LDG covers 256B = 2 sectors (vs 4 with the {2tid,2tid+1}
        // mapping): halves L1tex wavefronts per poll iteration. The smem
        // rebroadcast makes the mapping invisible to consumers.
        if (t > 0) {
            const unsigned exp_tag = (unsigned)(base + t);
            const u64* srcb = &g_tagged[(t - 1) & 1][0];
            u64 w0, w1;
            for (;;) {
                w0 = ld_relaxed64(srcb + tid);
                w1 = ld_relaxed64(srcb + tid + 1024);
                if ((unsigned)(w0 >> 32) == exp_tag && (unsigned)(w1 >> 32) == exp_tag)
                    break;
            }
            a_sf[tid]        = __uint_as_float((unsigned)w0);
            a_sf[tid + 1024] = __uint_as_float((unsigned)w1);
        }
        __syncthreads();                                 // bar A
        float4 a4 = (t > 0) ? *(const float4*)&a_sf[4 * slot]
                            : make_float4(0.f, 0.f, 0.f, 0.f);

        // ---- Phase B: recurrent matvec on register weights ----
        float v[8];
        #pragma unroll
        for (int i = 0; i < 8; i++)
            v[i] = fmaf(w4[i].x, a4.x,
                   fmaf(w4[i].y, a4.y,
                   fmaf(w4[i].z, a4.z, w4[i].w * a4.w)));

        // select-then-shuffle fold: 8 accumulators -> row sums in lanes 0..7
        #pragma unroll
        for (int k = 0; k < 4; k++) {
            float give = (lane & 1) ? v[2 * k] : v[2 * k + 1];
            float got  = __shfl_xor_sync(0xFFFFFFFFu, give, 1);
            v[k] = ((lane & 1) ? v[2 * k + 1] : v[2 * k]) + got;
        }
        #pragma unroll
        for (int k = 0; k < 2; k++) {
            float give = (lane & 2) ? v[2 * k] : v[2 * k + 1];
            float got  = __shfl_xor_sync(0xFFFFFFFFu, give, 2);
            v[k] = ((lane & 2) ? v[2 * k + 1] : v[2 * k]) + got;
        }
        float s;
        {
            float give = (lane & 4) ? v[0] : v[1];
            float got  = __shfl_xor_sync(0xFFFFFFFFu, give, 4);
            s = ((lane & 4) ? v[1] : v[0]) + got;
        }
        s += __shfl_xor_sync(0xFFFFFFFFu, s, 8);
        s += __shfl_xor_sync(0xFFFFFFFFu, s, 16);
        if (lane < 8) red_s[half * 8 + lane][warp & 15] = s;
        __syncthreads();                                 // bar B

        // ---- Phase C: final reduce + nonlinearity + publish (threads 0..15) ----
        if (tid < ROWS_CTA) {
            const int row = tid;
            float4 s0 = *(const float4*)&red_s[row][0];
            float4 s1 = *(const float4*)&red_s[row][4];
            float4 s2 = *(const float4*)&red_s[row][8];
            float4 s3 = *(const float4*)&red_s[row][12];
            float sx = ((s0.x + s1.x) + (s2.x + s3.x)) + ((s0.y + s1.y) + (s2.y + s3.y));
            float sy = ((s0.z + s1.z) + (s2.z + s3.z)) + ((s0.w + s1.w) + (s2.w + s3.w));
            float tot = sx + sy;

            const float nh = (1.0f - LEAK) * hid_s[row] + LEAK * (ipc + tot);
            const float na = fast_tanh(nh);
            hid_s[row] = nh;

            const int gr = r0 + row;
            st_relaxed64(&g_tagged[t & 1][gr],
                         ((u64)(unsigned)(base + t + 1) << 32) | (u64)__float_as_uint(na));
            out_act[(size_t)t * HID + gr] = na;
            out_hid[(size_t)t * HID + gr] = nh;

            // advance ip pipeline (slack: consumed 2 steps from issue)
            ipc = ipn;
            int tn = (t + 2 < T_STEPS) ? t + 2 : T_STEPS - 1;
            ipn = __ldcg(&g_ip[(size_t)tn * HID + gr]);
        }
        // No trailing barrier: a_sf/red_s overwrites for step t+1 are gated by
        // bar A / bar B of t+1, which Phase C threads reach only after their
        // step-t reads are value-bound. g_tagged slot overwrite (tag t+3) needs
        // the producer's step-(t+2) poll <= all CTAs published t+1 <= all
        // consumers finished their tag-(t+1) polls — no reader is lapped.
    }

    if (tid == 0) g_base[cta][0] = base + T_STEPS;   // advance tags for next replay
}

extern "C" void kernel_launch(void* const* d_in, const int* in_sizes, int n_in,
                              void* d_out, int out_size) {
    const float* input = (const float*)d_in[0];   // [4096, 128]
    const float* w_ih  = (const float*)d_in[1];   // [2048, 128]
    const float* b_ih  = (const float*)d_in[2];   // [2048]
    const float* w_hh  = (const float*)d_in[3];   // [2048, 2048]
    float* out = (float*)d_out;                   // [2, 4096, 2048]

    reservoir_kernel<<<NCTA, NTHREADS>>>(input, w_ih, b_ih, w_hh, out);
}